// round 13
// baseline (speedup 1.0000x reference)
#include <cuda_runtime.h>

#define NB 16
#define NS 4096
#define NTOK (NB*NS)
#define CHUNK 128
#define VS 68              // padded u32 stride for V rows (bf16x2), 16B-aligned rows
#define NCH (NS/CHUNK)
#define KFW (CHUNK/16*128) // K-frag words per chunk (1024)

// scratch (device globals: no allocation allowed)
__device__ float g_qrow[NTOK*8];            // tf32(q*log2e/sqrt2) [b][s][w] (Q operand)
__device__ unsigned int g_kfrag[NB*NS*8];   // tf32(q), mma-B-fragment order  (K operand)
__device__ unsigned short g_vhi[NB*8*NS];   // bf16(q)             [b][w][t]  (V operand)

typedef unsigned int u32;

__device__ __forceinline__ float ex2f(float x){float r; asm("ex2.approx.ftz.f32 %0,%1;":"=f"(r):"f"(x)); return r;}
__device__ __forceinline__ float tf32r(float x){u32 r; asm("cvt.rna.tf32.f32 %0,%1;":"=r"(r):"f"(x)); return __uint_as_float(r);}
// pack: result.lo = lo, result.hi = hi
__device__ __forceinline__ u32 pkbf(float hi, float lo){u32 r; asm("cvt.rn.bf16x2.f32 %0,%1,%2;":"=r"(r):"f"(hi),"f"(lo)); return r;}
__device__ __forceinline__ void cpa16(u32 dst, const void* src){
    asm volatile("cp.async.cg.shared.global [%0], [%1], 16;"::"r"(dst),"l"(src));
}
__device__ __forceinline__ void cpa_commit(){ asm volatile("cp.async.commit_group;"); }
__device__ __forceinline__ void cpa_wait1(){ asm volatile("cp.async.wait_group 1;"); }

__device__ __forceinline__ void mma_tf32(float* d, const u32* a, u32 b0, u32 b1){
    asm volatile("mma.sync.aligned.m16n8k8.row.col.f32.tf32.tf32.f32 "
        "{%0,%1,%2,%3},{%4,%5,%6,%7},{%8,%9},{%10,%11,%12,%13};"
        : "=f"(d[0]),"=f"(d[1]),"=f"(d[2]),"=f"(d[3])
        : "r"(a[0]),"r"(a[1]),"r"(a[2]),"r"(a[3]), "r"(b0),"r"(b1),
          "f"(0.f),"f"(0.f),"f"(0.f),"f"(0.f));
}
__device__ __forceinline__ void mma_bf16(float* d, const u32* a, u32 b0, u32 b1){
    asm volatile("mma.sync.aligned.m16n8k16.row.col.f32.bf16.bf16.f32 "
        "{%0,%1,%2,%3},{%4,%5,%6,%7},{%8,%9},{%0,%1,%2,%3};"
        : "+f"(d[0]),"+f"(d[1]),"+f"(d[2]),"+f"(d[3])
        : "r"(a[0]),"r"(a[1]),"r"(a[2]),"r"(a[3]), "r"(b0),"r"(b1));
}

// LUT exp2: p = T[round(z)] * (1 + ln2/64 * frac),  z = s2*64 + 544
__device__ __forceinline__ float lexp(float s2, const float* tb){
    float z = fmaf(s2, 64.0f, 544.0f);
    float y = z + 12582912.0f;                 // 1.5*2^23 magic (RN)
    u32  i = __float_as_uint(y) & 0xFFFu;
    float f = z - (y - 12582912.0f);           // in [-0.5, 0.5]
    float T = tb[i];
    return fmaf(T*f, 0.01083042469f, T);       // ln2/64
}

// ---------------------------------------------------------------------------
// Kernel 1: quantum features (prefix cosine products).
//   Emits: Q (tf32, pre-scaled), K (tf32, mma-fragment order, smem-staged for
//   coalesced global writes), V (bf16).
// ---------------------------------------------------------------------------
__global__ void feat_kernel(const float* __restrict__ x, const float* __restrict__ theta)
{
    __shared__ u32 stg[2048];                  // 256 tokens x 8 words, token-major
    int tid = threadIdx.x;
    int tok = blockIdx.x*256 + tid;
    float th[8];
    #pragma unroll
    for(int w=0;w<8;w++) th[w] = __ldg(&theta[w]);
    float4 x0 = *(const float4*)&x[tok*8];
    float4 x1 = *(const float4*)&x[tok*8+4];
    float c[8];
    c[0]=__cosf(x0.x+th[0]); c[1]=__cosf(x0.y+th[1]); c[2]=__cosf(x0.z+th[2]); c[3]=__cosf(x0.w+th[3]);
    c[4]=__cosf(x1.x+th[4]); c[5]=__cosf(x1.y+th[5]); c[6]=__cosf(x1.z+th[6]); c[7]=__cosf(x1.w+th[7]);
    float q[8];
    float p = c[0];
    #pragma unroll
    for(int w=1;w<8;w++){ p *= c[w]; q[w] = p; }
    float s = c[1];
    #pragma unroll
    for(int w=2;w<8;w++) s *= c[w];
    q[0] = s;                                   // CNOT-ring inverse image
    const float SC = 1.02013946f;               // log2(e)/sqrt(2)
    float qs[8];
    #pragma unroll
    for(int w=0;w<8;w++) qs[w]=tf32r(q[w]*SC);
    *(float4*)&g_qrow[tok*8]   = make_float4(qs[0],qs[1],qs[2],qs[3]);
    *(float4*)&g_qrow[tok*8+4] = make_float4(qs[4],qs[5],qs[6],qs[7]);
    int b = tok >> 12, t = tok & (NS-1);
    // stage token-major (2x STS.128), V scatter per-w coalesced
    u32 kq[8];
    #pragma unroll
    for(int w=0;w<8;w++){
        float qv = q[w];
        kq[w] = __float_as_uint(tf32r(qv));
        g_vhi[(b*8+w)*NS + t] = (unsigned short)(pkbf(0.f, qv) & 0xffffu);
    }
    *(uint4*)&stg[tid*8]   = make_uint4(kq[0],kq[1],kq[2],kq[3]);
    *(uint4*)&stg[tid*8+4] = make_uint4(kq[4],kq[5],kq[6],kq[7]);
    __syncthreads();
    // coalesced frag-order writeback: decode global word j -> (token, wire)
    u32* dst = &g_kfrag[b*NS*8 + ((blockIdx.x*256 & (NS-1))>>4)*128];
    #pragma unroll
    for(int k=0;k<8;k++){
        int j = tid + k*256;
        int w  = ((j>>2)&3) | ((j&1)<<2);
        int tl = ((j>>7)<<4) | (((j>>1)&1)<<3) | ((j>>4)&7);
        dst[j] = stg[tl*8 + w];
    }
}

// ---------------------------------------------------------------------------
// Kernel 2: flash attention via warp mma.sync + fused epilogue.
//   Per 16-t subtile: 1 LDS.128 + 2 tf32 mma -> S ; 6 ex2 (MUFU) +
//   2 LUT-exps (LSU/FMA) ; 4 cvt ; 1 bf16 mma. CHUNK=128 keeps smem ~19KB
//   so occupancy rises to ~7 CTAs/SM despite the 4.3KB table.
// ---------------------------------------------------------------------------
__global__ void __launch_bounds__(128, 7) attn_kernel(const float* __restrict__ W,
                                                      const float* __restrict__ bias,
                                                      float* __restrict__ out)
{
    __shared__ __align__(16) u32 skf[2][KFW];    // K fragments, 4KB/stage
    __shared__ __align__(16) u32 svh[2][8*VS];   // V bf16x2,    2.1KB/stage
    __shared__ float stable[1088];               // exp2 LUT, 4.3KB
    __shared__ float so[64*9];                   // o staging, stride 9

    const int b    = blockIdx.y;
    const int tid  = threadIdx.x;
    const int warp = tid >> 5, lane = tid & 31;
    const int g    = lane >> 2, c = lane & 3;
    const int row0 = blockIdx.x*64 + warp*16;

    // hoisted chunk-load addressing
    const u32*            kfsrc = &g_kfrag[b*NS*8] + tid*4;
    const unsigned short* vsrc  = &g_vhi[(b*8 + (tid>>4))*NS] + (tid&15)*8;
    u32 skb  = (u32)__cvta_generic_to_shared(&skf[0][0]) + (u32)(tid*16);
    u32 svhb = (u32)__cvta_generic_to_shared(&svh[0][0]) + (u32)(((tid>>4)*VS + (tid&15)*4)*4);
    const u32 KSTG = KFW*4u, VSTG = 8*VS*4u;

    auto load_chunk = [&](int ch, int st){
        const u32*            ks = kfsrc + ch*(CHUNK*8);
        const unsigned short* vs = vsrc  + ch*CHUNK;
        u32 kb = skb  + (st ? KSTG : 0u);
        u32 hb = svhb + (st ? VSTG : 0u);
        cpa16(kb,        ks);
        cpa16(kb + 2048, ks + 512);
        cpa16(hb,        vs);
        cpa_commit();
    };

    load_chunk(0, 0);

    // build exp2 table (once per CTA) while chunk 0 streams in
    for(int i=tid; i<1088; i+=128) stable[i] = ex2f((float)(i-544) * 0.015625f);

    // Q fragment (held whole kernel)
    const float* qr = &g_qrow[(b*NS+row0)*8];
    u32 qa[4];
    qa[0] = __float_as_uint(qr[ g   *8 + c  ]);
    qa[1] = __float_as_uint(qr[(g+8)*8 + c  ]);
    qa[2] = __float_as_uint(qr[ g   *8 + c+4]);
    qa[3] = __float_as_uint(qr[(g+8)*8 + c+4]);

    float num0[4] = {0.f,0.f,0.f,0.f};
    float num1[4] = {0.f,0.f,0.f,0.f};
    float d0l=0.f, d0h=0.f, d1l=0.f, d1h=0.f;

    for(int ch=0; ch<NCH; ch++){
        int st = ch & 1;
        if(ch+1 < NCH) load_chunk(ch+1, (ch+1)&1);
        else           cpa_commit();           // keep wait count uniform
        cpa_wait1();
        __syncthreads();

        const u32* KF = &skf[st][0];
        const u32* VH = &svh[st][0];

        #pragma unroll 2
        for(int pair=0; pair<CHUNK/32; pair++){
            const int tA = pair*32, tB = pair*32 + 16;
            uint4 fA = *(const uint4*)&KF[(pair*2  )*128 + lane*4];
            uint4 fB = *(const uint4*)&KF[(pair*2+1)*128 + lane*4];

            float Al[4], Ar[4], Bl[4], Br[4];
            mma_tf32(Al, qa, fA.x, fA.y);
            mma_tf32(Ar, qa, fA.z, fA.w);
            mma_tf32(Bl, qa, fB.x, fB.y);
            mma_tf32(Br, qa, fB.z, fB.w);

            // 12 exps on MUFU, 4 via LUT (LSU/FMA pipes)
            Al[0]=ex2f(Al[0]); Al[1]=ex2f(Al[1]); Al[2]=ex2f(Al[2]); Al[3]=ex2f(Al[3]);
            Ar[0]=ex2f(Ar[0]); Ar[1]=ex2f(Ar[1]);
            Ar[2]=lexp(Ar[2],stable); Ar[3]=lexp(Ar[3],stable);
            Bl[0]=ex2f(Bl[0]); Bl[1]=ex2f(Bl[1]); Bl[2]=ex2f(Bl[2]); Bl[3]=ex2f(Bl[3]);
            Br[0]=ex2f(Br[0]); Br[1]=ex2f(Br[1]);
            Br[2]=lexp(Br[2],stable); Br[3]=lexp(Br[3],stable);

            d0l += Al[0]+Al[1]+Ar[0]+Ar[1];
            d0h += Al[2]+Al[3]+Ar[2]+Ar[3];
            d1l += Bl[0]+Bl[1]+Br[0]+Br[1];
            d1h += Bl[2]+Bl[3]+Br[2]+Br[3];

            u32 pA[4], pB[4];
            pA[0]=pkbf(Al[1],Al[0]); pA[1]=pkbf(Al[3],Al[2]);
            pA[2]=pkbf(Ar[1],Ar[0]); pA[3]=pkbf(Ar[3],Ar[2]);
            pB[0]=pkbf(Bl[1],Bl[0]); pB[1]=pkbf(Bl[3],Bl[2]);
            pB[2]=pkbf(Br[1],Br[0]); pB[3]=pkbf(Br[3],Br[2]);

            int viA = g*VS + (tA>>1);
            int viB = g*VS + (tB>>1);
            mma_bf16(num0, pA, VH[viA + c], VH[viA + 4 + c]);
            mma_bf16(num1, pB, VH[viB + c], VH[viB + 4 + c]);
        }
        __syncthreads();
    }

    float denl = d0l + d1l, denh = d0h + d1h;
    denl += __shfl_xor_sync(0xffffffffu, denl, 1);
    denl += __shfl_xor_sync(0xffffffffu, denl, 2);
    denh += __shfl_xor_sync(0xffffffffu, denh, 1);
    denh += __shfl_xor_sync(0xffffffffu, denh, 2);
    float invl = 1.0f/denl, invh = 1.0f/denh;

    // stage normalized o tile: so[localRow][e], stride 9
    int lr = warp*16 + g;
    so[ lr   *9 + 2*c] = (num0[0]+num1[0])*invl;  so[ lr   *9 + 2*c+1] = (num0[1]+num1[1])*invl;
    so[(lr+8)*9 + 2*c] = (num0[2]+num1[2])*invh;  so[(lr+8)*9 + 2*c+1] = (num0[3]+num1[3])*invh;
    __syncthreads();

    // fused epilogue: out[b, e*512 + 8*bx + m, :] = bias + so[8m+j][e] . W[:,j]
    if(tid < 64){
        int e = tid >> 3, m = tid & 7;
        float y[8];
        #pragma unroll
        for(int j=0;j<8;j++) y[j] = so[(8*m+j)*9 + e];
        float r[8];
        #pragma unroll
        for(int ep=0;ep<8;ep++){
            float a = __ldg(&bias[ep]);
            #pragma unroll
            for(int j=0;j<8;j++) a = fmaf(y[j], __ldg(&W[ep*8+j]), a);
            r[ep]=a;
        }
        int i = e*512 + blockIdx.x*8 + m;
        float* op = &out[(b*NS + i)*8];
        *(float4*)op     = make_float4(r[0],r[1],r[2],r[3]);
        *(float4*)(op+4) = make_float4(r[4],r[5],r[6],r[7]);
    }
}

extern "C" void kernel_launch(void* const* d_in, const int* in_sizes, int n_in,
                              void* d_out, int out_size)
{
    const float* x     = (const float*)d_in[0];
    const float* theta = (const float*)d_in[1];
    const float* w     = (const float*)d_in[2];
    const float* bias  = (const float*)d_in[3];
    float* out = (float*)d_out;

    feat_kernel<<<NTOK/256, 256>>>(x, theta);
    dim3 g(NS/64, NB);
    attn_kernel<<<g, 128>>>(w, bias, out);
}

// round 14
// speedup vs baseline: 1.3768x; 1.3768x over previous
#include <cuda_runtime.h>

#define NB 16
#define NS 4096
#define NTOK (NB*NS)
#define CHUNK 256
#define VS 132             // padded u32 stride for V rows (f16x2)
#define NCH (NS/CHUNK)
#define KFW (CHUNK/16*128) // K-frag words per chunk (2048)

// scratch (device globals: no allocation allowed)
__device__ float g_qrow[NTOK*8];            // tf32(q*log2e/sqrt2) [b][s][w] (Q operand)
__device__ unsigned int g_kfrag[NB*NS*8];   // tf32(q), mma-B-fragment order  (K operand)
__device__ unsigned short g_vhi[NB*8*NS];   // fp16(q)             [b][w][t]  (V operand)

typedef unsigned int u32;

__device__ __forceinline__ float ex2f(float x){float r; asm("ex2.approx.ftz.f32 %0,%1;":"=f"(r):"f"(x)); return r;}
__device__ __forceinline__ float tf32r(float x){u32 r; asm("cvt.rna.tf32.f32 %0,%1;":"=r"(r):"f"(x)); return __uint_as_float(r);}
// pack f16x2: result.lo = lo, result.hi = hi
__device__ __forceinline__ u32 pkhf(float hi, float lo){u32 r; asm("cvt.rn.f16x2.f32 %0,%1,%2;":"=r"(r):"f"(hi),"f"(lo)); return r;}
// two exponentials in ONE MUFU op
__device__ __forceinline__ u32 ex2h2(u32 a){u32 r; asm("ex2.approx.f16x2 %0,%1;":"=r"(r):"r"(a)); return r;}
__device__ __forceinline__ void cpa16(u32 dst, const void* src){
    asm volatile("cp.async.cg.shared.global [%0], [%1], 16;"::"r"(dst),"l"(src));
}
__device__ __forceinline__ void cpa_commit(){ asm volatile("cp.async.commit_group;"); }
__device__ __forceinline__ void cpa_wait1(){ asm volatile("cp.async.wait_group 1;"); }

__device__ __forceinline__ void mma_tf32(float* d, const u32* a, u32 b0, u32 b1){
    asm volatile("mma.sync.aligned.m16n8k8.row.col.f32.tf32.tf32.f32 "
        "{%0,%1,%2,%3},{%4,%5,%6,%7},{%8,%9},{%10,%11,%12,%13};"
        : "=f"(d[0]),"=f"(d[1]),"=f"(d[2]),"=f"(d[3])
        : "r"(a[0]),"r"(a[1]),"r"(a[2]),"r"(a[3]), "r"(b0),"r"(b1),
          "f"(0.f),"f"(0.f),"f"(0.f),"f"(0.f));
}
__device__ __forceinline__ void mma_f16(float* d, const u32* a, u32 b0, u32 b1){
    asm volatile("mma.sync.aligned.m16n8k16.row.col.f32.f16.f16.f32 "
        "{%0,%1,%2,%3},{%4,%5,%6,%7},{%8,%9},{%0,%1,%2,%3};"
        : "+f"(d[0]),"+f"(d[1]),"+f"(d[2]),"+f"(d[3])
        : "r"(a[0]),"r"(a[1]),"r"(a[2]),"r"(a[3]), "r"(b0),"r"(b1));
}

// ---------------------------------------------------------------------------
// Kernel 1: quantum features (prefix cosine products).
//   Emits: Q (tf32, pre-scaled), K (tf32, mma-fragment order via smem stage),
//   V (fp16).
// ---------------------------------------------------------------------------
__global__ void feat_kernel(const float* __restrict__ x, const float* __restrict__ theta)
{
    __shared__ u32 stg[2048];                  // 256 tokens x 8 words, token-major
    int tid = threadIdx.x;
    int tok = blockIdx.x*256 + tid;
    float th[8];
    #pragma unroll
    for(int w=0;w<8;w++) th[w] = __ldg(&theta[w]);
    float4 x0 = *(const float4*)&x[tok*8];
    float4 x1 = *(const float4*)&x[tok*8+4];
    float c[8];
    c[0]=__cosf(x0.x+th[0]); c[1]=__cosf(x0.y+th[1]); c[2]=__cosf(x0.z+th[2]); c[3]=__cosf(x0.w+th[3]);
    c[4]=__cosf(x1.x+th[4]); c[5]=__cosf(x1.y+th[5]); c[6]=__cosf(x1.z+th[6]); c[7]=__cosf(x1.w+th[7]);
    float q[8];
    float p = c[0];
    #pragma unroll
    for(int w=1;w<8;w++){ p *= c[w]; q[w] = p; }
    float s = c[1];
    #pragma unroll
    for(int w=2;w<8;w++) s *= c[w];
    q[0] = s;                                   // CNOT-ring inverse image
    const float SC = 1.02013946f;               // log2(e)/sqrt(2)
    float qs[8];
    #pragma unroll
    for(int w=0;w<8;w++) qs[w]=tf32r(q[w]*SC);
    *(float4*)&g_qrow[tok*8]   = make_float4(qs[0],qs[1],qs[2],qs[3]);
    *(float4*)&g_qrow[tok*8+4] = make_float4(qs[4],qs[5],qs[6],qs[7]);
    int b = tok >> 12, t = tok & (NS-1);
    u32 kq[8];
    #pragma unroll
    for(int w=0;w<8;w++){
        float qv = q[w];
        kq[w] = __float_as_uint(tf32r(qv));
        g_vhi[(b*8+w)*NS + t] = (unsigned short)(pkhf(0.f, qv) & 0xffffu);
    }
    *(uint4*)&stg[tid*8]   = make_uint4(kq[0],kq[1],kq[2],kq[3]);
    *(uint4*)&stg[tid*8+4] = make_uint4(kq[4],kq[5],kq[6],kq[7]);
    __syncthreads();
    // coalesced frag-order writeback: decode global word j -> (token, wire)
    u32* dst = &g_kfrag[b*NS*8 + ((blockIdx.x*256 & (NS-1))>>4)*128];
    #pragma unroll
    for(int k=0;k<8;k++){
        int j = tid + k*256;
        int w  = ((j>>2)&3) | ((j&1)<<2);
        int tl = ((j>>7)<<4) | (((j>>1)&1)<<3) | ((j>>4)&7);
        dst[j] = stg[tl*8 + w];
    }
}

// ---------------------------------------------------------------------------
// Kernel 2: flash attention via warp mma.sync + fused epilogue.
//   Per 16-t subtile: 0.5 LDS.128 (K frag) + 2 tf32 mma -> S(f32) ;
//   4x cvt.f16x2 ; 4x ex2.approx.f16x2 (HALF the MUFU work) ->
//   P f16x2 = A-fragment directly ; num-mma + ones-mma (den) in f16.
// ---------------------------------------------------------------------------
__global__ void __launch_bounds__(128, 7) attn_kernel(const float* __restrict__ W,
                                                      const float* __restrict__ bias,
                                                      float* __restrict__ out)
{
    __shared__ __align__(16) u32 skf[2][KFW];    // K fragments, 8KB/stage
    __shared__ __align__(16) u32 svh[2][8*VS];   // V f16x2, 2.1KB/stage
    __shared__ float so[64*9];                   // o staging, stride 9

    const int b    = blockIdx.y;
    const int tid  = threadIdx.x;
    const int warp = tid >> 5, lane = tid & 31;
    const int g    = lane >> 2, c = lane & 3;
    const int row0 = blockIdx.x*64 + warp*16;

    // hoisted chunk-load addressing
    const int vr = tid >> 5, vo = tid & 31;
    const u32*            kfsrc = &g_kfrag[b*NS*8] + tid*4;
    const unsigned short* vsrc  = &g_vhi [b*8*NS + vr*NS] + vo*8;
    u32 skb  = (u32)__cvta_generic_to_shared(&skf[0][0]) + (u32)(tid*16);
    u32 svhb = (u32)__cvta_generic_to_shared(&svh[0][0]) + (u32)((vr*VS + vo*4)*4);
    const u32 KSTG = KFW*4u, VSTG = 8*VS*4u;

    // Q fragment (held whole kernel)
    const float* qr = &g_qrow[(b*NS+row0)*8];
    u32 qa[4];
    qa[0] = __float_as_uint(qr[ g   *8 + c  ]);
    qa[1] = __float_as_uint(qr[(g+8)*8 + c  ]);
    qa[2] = __float_as_uint(qr[ g   *8 + c+4]);
    qa[3] = __float_as_uint(qr[(g+8)*8 + c+4]);

    float num0[4] = {0.f,0.f,0.f,0.f};
    float num1[4] = {0.f,0.f,0.f,0.f};
    float den0[4] = {0.f,0.f,0.f,0.f};
    float den1[4] = {0.f,0.f,0.f,0.f};
    const u32 ONEH = 0x3C003C00u;                // f16x2 {1,1}

    auto load_chunk = [&](int ch, int st){
        const u32*            ks = kfsrc + ch*(CHUNK*8);
        const unsigned short* vs = vsrc  + ch*CHUNK;
        u32 kb = skb  + (st ? KSTG : 0u);
        u32 hb = svhb + (st ? VSTG : 0u);
        #pragma unroll
        for(int k=0;k<4;k++) cpa16(kb + (u32)(k*512)*4u, ks + k*512);
        #pragma unroll
        for(int k=0;k<2;k++) cpa16(hb + (u32)(4*k*VS)*4u, vs + 4*k*NS);
        cpa_commit();
    };

    load_chunk(0, 0);

    for(int ch=0; ch<NCH; ch++){
        int st = ch & 1;
        if(ch+1 < NCH) load_chunk(ch+1, (ch+1)&1);
        else           cpa_commit();           // keep wait count uniform
        cpa_wait1();
        __syncthreads();

        const u32* KF = &skf[st][0];
        const u32* VH = &svh[st][0];

        #pragma unroll 2
        for(int pair=0; pair<CHUNK/32; pair++){
            const int tA = pair*32, tB = pair*32 + 16;
            uint4 fA = *(const uint4*)&KF[(pair*2  )*128 + lane*4];
            uint4 fB = *(const uint4*)&KF[(pair*2+1)*128 + lane*4];

            float Al[4], Ar[4], Bl[4], Br[4];
            mma_tf32(Al, qa, fA.x, fA.y);
            mma_tf32(Ar, qa, fA.z, fA.w);
            mma_tf32(Bl, qa, fB.x, fB.y);
            mma_tf32(Br, qa, fB.z, fB.w);

            // P = exp2(S): pack to f16x2, ONE MUFU op per pair
            u32 pA[4], pB[4];
            pA[0] = ex2h2(pkhf(Al[1],Al[0]));   // row g,   k 2c..2c+1
            pA[1] = ex2h2(pkhf(Al[3],Al[2]));   // row g+8
            pA[2] = ex2h2(pkhf(Ar[1],Ar[0]));   // row g,   k 2c+8..
            pA[3] = ex2h2(pkhf(Ar[3],Ar[2]));
            pB[0] = ex2h2(pkhf(Bl[1],Bl[0]));
            pB[1] = ex2h2(pkhf(Bl[3],Bl[2]));
            pB[2] = ex2h2(pkhf(Br[1],Br[0]));
            pB[3] = ex2h2(pkhf(Br[3],Br[2]));

            int viA = g*VS + (tA>>1);
            int viB = g*VS + (tB>>1);
            mma_f16(num0, pA, VH[viA + c], VH[viA + 4 + c]);
            mma_f16(num1, pB, VH[viB + c], VH[viB + 4 + c]);
            mma_f16(den0, pA, ONEH, ONEH);      // row sums -> den
            mma_f16(den1, pB, ONEH, ONEH);
        }
        __syncthreads();
    }

    float invl = 1.0f/(den0[0]+den1[0]);
    float invh = 1.0f/(den0[2]+den1[2]);

    // stage normalized o tile: so[localRow][e], stride 9
    int lr = warp*16 + g;
    so[ lr   *9 + 2*c] = (num0[0]+num1[0])*invl;  so[ lr   *9 + 2*c+1] = (num0[1]+num1[1])*invl;
    so[(lr+8)*9 + 2*c] = (num0[2]+num1[2])*invh;  so[(lr+8)*9 + 2*c+1] = (num0[3]+num1[3])*invh;
    __syncthreads();

    // fused epilogue: out[b, e*512 + 8*bx + m, :] = bias + so[8m+j][e] . W[:,j]
    if(tid < 64){
        int e = tid >> 3, m = tid & 7;
        float y[8];
        #pragma unroll
        for(int j=0;j<8;j++) y[j] = so[(8*m+j)*9 + e];
        float r[8];
        #pragma unroll
        for(int ep=0;ep<8;ep++){
            float a = __ldg(&bias[ep]);
            #pragma unroll
            for(int j=0;j<8;j++) a = fmaf(y[j], __ldg(&W[ep*8+j]), a);
            r[ep]=a;
        }
        int i = e*512 + blockIdx.x*8 + m;
        float* op = &out[(b*NS + i)*8];
        *(float4*)op     = make_float4(r[0],r[1],r[2],r[3]);
        *(float4*)(op+4) = make_float4(r[4],r[5],r[6],r[7]);
    }
}

extern "C" void kernel_launch(void* const* d_in, const int* in_sizes, int n_in,
                              void* d_out, int out_size)
{
    const float* x     = (const float*)d_in[0];
    const float* theta = (const float*)d_in[1];
    const float* w     = (const float*)d_in[2];
    const float* bias  = (const float*)d_in[3];
    float* out = (float*)d_out;

    feat_kernel<<<NTOK/256, 256>>>(x, theta);
    dim3 g(NS/64, NB);
    attn_kernel<<<g, 128>>>(w, bias, out);
}

// round 15
// speedup vs baseline: 1.4407x; 1.0464x over previous
#include <cuda_runtime.h>

#define NB 16
#define NS 4096
#define NTOK (NB*NS)
#define CHUNK 256
#define VS 132             // padded u32 stride for V rows (f16x2)
#define NCH (NS/CHUNK)
#define KFW (CHUNK/16*128) // K-frag words per chunk (2048)

// scratch (device globals: no allocation allowed)
__device__ float g_qrow[NTOK*8];            // tf32(q*log2e/sqrt2) [b][s][w] (Q operand)
__device__ unsigned int g_kfrag[NB*NS*8];   // tf32(q), mma-B-fragment order  (K operand)
__device__ unsigned short g_vhi[NB*8*NS];   // fp16(q)             [b][w][t]  (V operand)

typedef unsigned int u32;

__device__ __forceinline__ float ex2f(float x){float r; asm("ex2.approx.ftz.f32 %0,%1;":"=f"(r):"f"(x)); return r;}
__device__ __forceinline__ float tf32r(float x){u32 r; asm("cvt.rna.tf32.f32 %0,%1;":"=r"(r):"f"(x)); return __uint_as_float(r);}
// pack f16x2: result.lo = lo, result.hi = hi
__device__ __forceinline__ u32 pkhf(float hi, float lo){u32 r; asm("cvt.rn.f16x2.f32 %0,%1,%2;":"=r"(r):"f"(hi),"f"(lo)); return r;}
// two exponentials in ONE MUFU op
__device__ __forceinline__ u32 ex2h2(u32 a){u32 r; asm("ex2.approx.f16x2 %0,%1;":"=r"(r):"r"(a)); return r;}
// f16x2 add (fma pipe)
__device__ __forceinline__ u32 hadd2(u32 a, u32 b){u32 r; asm("add.rn.f16x2 %0,%1,%2;":"=r"(r):"r"(a),"r"(b)); return r;}
// f16x2 -> f32 sum of both halves
__device__ __forceinline__ float hsum2(u32 a){
    float lo, hi;
    asm("{ .reg .f16 l, h; mov.b32 {l,h}, %2; cvt.f32.f16 %0, l; cvt.f32.f16 %1, h; }"
        : "=f"(lo), "=f"(hi) : "r"(a));
    return lo + hi;
}
__device__ __forceinline__ void cpa16(u32 dst, const void* src){
    asm volatile("cp.async.cg.shared.global [%0], [%1], 16;"::"r"(dst),"l"(src));
}
__device__ __forceinline__ void cpa_commit(){ asm volatile("cp.async.commit_group;"); }
__device__ __forceinline__ void cpa_wait1(){ asm volatile("cp.async.wait_group 1;"); }

__device__ __forceinline__ void mma_tf32(float* d, const u32* a, u32 b0, u32 b1){
    asm volatile("mma.sync.aligned.m16n8k8.row.col.f32.tf32.tf32.f32 "
        "{%0,%1,%2,%3},{%4,%5,%6,%7},{%8,%9},{%10,%11,%12,%13};"
        : "=f"(d[0]),"=f"(d[1]),"=f"(d[2]),"=f"(d[3])
        : "r"(a[0]),"r"(a[1]),"r"(a[2]),"r"(a[3]), "r"(b0),"r"(b1),
          "f"(0.f),"f"(0.f),"f"(0.f),"f"(0.f));
}
__device__ __forceinline__ void mma_f16(float* d, const u32* a, u32 b0, u32 b1){
    asm volatile("mma.sync.aligned.m16n8k16.row.col.f32.f16.f16.f32 "
        "{%0,%1,%2,%3},{%4,%5,%6,%7},{%8,%9},{%0,%1,%2,%3};"
        : "+f"(d[0]),"+f"(d[1]),"+f"(d[2]),"+f"(d[3])
        : "r"(a[0]),"r"(a[1]),"r"(a[2]),"r"(a[3]), "r"(b0),"r"(b1));
}

// ---------------------------------------------------------------------------
// Kernel 1: quantum features (prefix cosine products).
//   Emits: Q (tf32, pre-scaled), K (tf32, mma-fragment order via smem stage),
//   V (fp16).
// ---------------------------------------------------------------------------
__global__ void feat_kernel(const float* __restrict__ x, const float* __restrict__ theta)
{
    __shared__ u32 stg[2048];                  // 256 tokens x 8 words, token-major
    int tid = threadIdx.x;
    int tok = blockIdx.x*256 + tid;
    float th[8];
    #pragma unroll
    for(int w=0;w<8;w++) th[w] = __ldg(&theta[w]);
    float4 x0 = *(const float4*)&x[tok*8];
    float4 x1 = *(const float4*)&x[tok*8+4];
    float c[8];
    c[0]=__cosf(x0.x+th[0]); c[1]=__cosf(x0.y+th[1]); c[2]=__cosf(x0.z+th[2]); c[3]=__cosf(x0.w+th[3]);
    c[4]=__cosf(x1.x+th[4]); c[5]=__cosf(x1.y+th[5]); c[6]=__cosf(x1.z+th[6]); c[7]=__cosf(x1.w+th[7]);
    float q[8];
    float p = c[0];
    #pragma unroll
    for(int w=1;w<8;w++){ p *= c[w]; q[w] = p; }
    float s = c[1];
    #pragma unroll
    for(int w=2;w<8;w++) s *= c[w];
    q[0] = s;                                   // CNOT-ring inverse image
    const float SC = 1.02013946f;               // log2(e)/sqrt(2)
    float qs[8];
    #pragma unroll
    for(int w=0;w<8;w++) qs[w]=tf32r(q[w]*SC);
    *(float4*)&g_qrow[tok*8]   = make_float4(qs[0],qs[1],qs[2],qs[3]);
    *(float4*)&g_qrow[tok*8+4] = make_float4(qs[4],qs[5],qs[6],qs[7]);
    int b = tok >> 12, t = tok & (NS-1);
    u32 kq[8];
    #pragma unroll
    for(int w=0;w<8;w++){
        float qv = q[w];
        kq[w] = __float_as_uint(tf32r(qv));
        g_vhi[(b*8+w)*NS + t] = (unsigned short)(pkhf(0.f, qv) & 0xffffu);
    }
    *(uint4*)&stg[tid*8]   = make_uint4(kq[0],kq[1],kq[2],kq[3]);
    *(uint4*)&stg[tid*8+4] = make_uint4(kq[4],kq[5],kq[6],kq[7]);
    __syncthreads();
    // coalesced frag-order writeback: decode global word j -> (token, wire)
    u32* dst = &g_kfrag[b*NS*8 + ((blockIdx.x*256 & (NS-1))>>4)*128];
    #pragma unroll
    for(int k=0;k<8;k++){
        int j = tid + k*256;
        int w  = ((j>>2)&3) | ((j&1)<<2);
        int tl = ((j>>7)<<4) | (((j>>1)&1)<<3) | ((j>>4)&7);
        dst[j] = stg[tl*8 + w];
    }
}

// ---------------------------------------------------------------------------
// Kernel 2: flash attention via warp mma.sync + fused epilogue.
//   Per 16-t subtile: 0.5 LDS.128 + 2 tf32 mma -> S(f32) ; 4 cvt.f16x2 ;
//   4 ex2.approx.f16x2 ; 1 f16 num-mma. den via HADD2 on the idle FMA pipe
//   (f16x2 accumulators, <=32 terms/half per chunk, flushed to f32 per chunk).
// ---------------------------------------------------------------------------
__global__ void __launch_bounds__(128, 8) attn_kernel(const float* __restrict__ W,
                                                      const float* __restrict__ bias,
                                                      float* __restrict__ out)
{
    __shared__ __align__(16) u32 skf[2][KFW];    // K fragments, 8KB/stage
    __shared__ __align__(16) u32 svh[2][8*VS];   // V f16x2, 2.1KB/stage
    __shared__ float so[64*9];                   // o staging, stride 9

    const int b    = blockIdx.y;
    const int tid  = threadIdx.x;
    const int warp = tid >> 5, lane = tid & 31;
    const int g    = lane >> 2, c = lane & 3;
    const int row0 = blockIdx.x*64 + warp*16;

    // hoisted chunk-load addressing
    const int vr = tid >> 5, vo = tid & 31;
    const u32*            kfsrc = &g_kfrag[b*NS*8] + tid*4;
    const unsigned short* vsrc  = &g_vhi [b*8*NS + vr*NS] + vo*8;
    u32 skb  = (u32)__cvta_generic_to_shared(&skf[0][0]) + (u32)(tid*16);
    u32 svhb = (u32)__cvta_generic_to_shared(&svh[0][0]) + (u32)((vr*VS + vo*4)*4);
    const u32 KSTG = KFW*4u, VSTG = 8*VS*4u;

    // Q fragment (held whole kernel)
    const float* qr = &g_qrow[(b*NS+row0)*8];
    u32 qa[4];
    qa[0] = __float_as_uint(qr[ g   *8 + c  ]);
    qa[1] = __float_as_uint(qr[(g+8)*8 + c  ]);
    qa[2] = __float_as_uint(qr[ g   *8 + c+4]);
    qa[3] = __float_as_uint(qr[(g+8)*8 + c+4]);

    float num0[4] = {0.f,0.f,0.f,0.f};
    float num1[4] = {0.f,0.f,0.f,0.f};
    float dfl = 0.f, dfh = 0.f;                  // f32 den (flushed per chunk)

    auto load_chunk = [&](int ch, int st){
        const u32*            ks = kfsrc + ch*(CHUNK*8);
        const unsigned short* vs = vsrc  + ch*CHUNK;
        u32 kb = skb  + (st ? KSTG : 0u);
        u32 hb = svhb + (st ? VSTG : 0u);
        #pragma unroll
        for(int k=0;k<4;k++) cpa16(kb + (u32)(k*512)*4u, ks + k*512);
        #pragma unroll
        for(int k=0;k<2;k++) cpa16(hb + (u32)(4*k*VS)*4u, vs + 4*k*NS);
        cpa_commit();
    };

    load_chunk(0, 0);

    for(int ch=0; ch<NCH; ch++){
        int st = ch & 1;
        if(ch+1 < NCH) load_chunk(ch+1, (ch+1)&1);
        else           cpa_commit();           // keep wait count uniform
        cpa_wait1();
        __syncthreads();

        const u32* KF = &skf[st][0];
        const u32* VH = &svh[st][0];

        u32 hd0 = 0u, hd1 = 0u;                 // f16x2 den accumulators (rows g, g+8)

        #pragma unroll 2
        for(int pair=0; pair<CHUNK/32; pair++){
            const int tA = pair*32, tB = pair*32 + 16;
            uint4 fA = *(const uint4*)&KF[(pair*2  )*128 + lane*4];
            uint4 fB = *(const uint4*)&KF[(pair*2+1)*128 + lane*4];

            float Al[4], Ar[4], Bl[4], Br[4];
            mma_tf32(Al, qa, fA.x, fA.y);
            mma_tf32(Ar, qa, fA.z, fA.w);
            mma_tf32(Bl, qa, fB.x, fB.y);
            mma_tf32(Br, qa, fB.z, fB.w);

            // P = exp2(S): pack to f16x2, ONE MUFU op per pair of exps
            u32 pA[4], pB[4];
            pA[0] = ex2h2(pkhf(Al[1],Al[0]));   // row g,   t 2c,2c+1
            pA[1] = ex2h2(pkhf(Al[3],Al[2]));   // row g+8
            pA[2] = ex2h2(pkhf(Ar[1],Ar[0]));   // row g,   t 2c+8..
            pA[3] = ex2h2(pkhf(Ar[3],Ar[2]));
            pB[0] = ex2h2(pkhf(Bl[1],Bl[0]));
            pB[1] = ex2h2(pkhf(Bl[3],Bl[2]));
            pB[2] = ex2h2(pkhf(Br[1],Br[0]));
            pB[3] = ex2h2(pkhf(Br[3],Br[2]));

            // den on FMA pipe (HADD2); <=32 terms/half per chunk -> no overflow
            hd0 = hadd2(hd0, pA[0]); hd0 = hadd2(hd0, pA[2]);
            hd1 = hadd2(hd1, pA[1]); hd1 = hadd2(hd1, pA[3]);
            hd0 = hadd2(hd0, pB[0]); hd0 = hadd2(hd0, pB[2]);
            hd1 = hadd2(hd1, pB[1]); hd1 = hadd2(hd1, pB[3]);

            int viA = g*VS + (tA>>1);
            int viB = g*VS + (tB>>1);
            mma_f16(num0, pA, VH[viA + c], VH[viA + 4 + c]);
            mma_f16(num1, pB, VH[viB + c], VH[viB + 4 + c]);
        }
        dfl += hsum2(hd0);                      // flush to f32 each chunk
        dfh += hsum2(hd1);
        __syncthreads();
    }

    // reduce den across the 4 lanes sharing a row
    float denl = dfl, denh = dfh;
    denl += __shfl_xor_sync(0xffffffffu, denl, 1);
    denl += __shfl_xor_sync(0xffffffffu, denl, 2);
    denh += __shfl_xor_sync(0xffffffffu, denh, 1);
    denh += __shfl_xor_sync(0xffffffffu, denh, 2);
    float invl = 1.0f/denl, invh = 1.0f/denh;

    // stage normalized o tile: so[localRow][e], stride 9
    int lr = warp*16 + g;
    so[ lr   *9 + 2*c] = (num0[0]+num1[0])*invl;  so[ lr   *9 + 2*c+1] = (num0[1]+num1[1])*invl;
    so[(lr+8)*9 + 2*c] = (num0[2]+num1[2])*invh;  so[(lr+8)*9 + 2*c+1] = (num0[3]+num1[3])*invh;
    __syncthreads();

    // fused epilogue: out[b, e*512 + 8*bx + m, :] = bias + so[8m+j][e] . W[:,j]
    if(tid < 64){
        int e = tid >> 3, m = tid & 7;
        float y[8];
        #pragma unroll
        for(int j=0;j<8;j++) y[j] = so[(8*m+j)*9 + e];
        float r[8];
        #pragma unroll
        for(int ep=0;ep<8;ep++){
            float a = __ldg(&bias[ep]);
            #pragma unroll
            for(int j=0;j<8;j++) a = fmaf(y[j], __ldg(&W[ep*8+j]), a);
            r[ep]=a;
        }
        int i = e*512 + blockIdx.x*8 + m;
        float* op = &out[(b*NS + i)*8];
        *(float4*)op     = make_float4(r[0],r[1],r[2],r[3]);
        *(float4*)(op+4) = make_float4(r[4],r[5],r[6],r[7]);
    }
}

extern "C" void kernel_launch(void* const* d_in, const int* in_sizes, int n_in,
                              void* d_out, int out_size)
{
    const float* x     = (const float*)d_in[0];
    const float* theta = (const float*)d_in[1];
    const float* w     = (const float*)d_in[2];
    const float* bias  = (const float*)d_in[3];
    float* out = (float*)d_out;

    feat_kernel<<<NTOK/256, 256>>>(x, theta);
    dim3 g(NS/64, NB);
    attn_kernel<<<g, 128>>>(w, bias, out);
}